// round 7
// baseline (speedup 1.0000x reference)
#include <cuda_runtime.h>

#define N_ROWS 8192
#define F_DIM  512
#define H1_DIM 512
#define SU_DIM 256
#define T_STEPS 16
#define BETA_F 0.95f
#define THR_F  1.0f

// ---------------- scratch (static device globals; no allocations) ----------------
__device__ unsigned g_spk1[N_ROWS * T_STEPS * (H1_DIM / 32)];  // 8 MB  [n][t][w]
__device__ float    g_sf[N_ROWS * SU_DIM];                     // 8 MB
__device__ float    g_W2T[H1_DIM * SU_DIM];                    // [j][i]
__device__ float    g_WeffT[SU_DIM * F_DIM];                   // [i][f]
__device__ float    g_beff[F_DIM];

// ---------------- fused prep: wefft (0..511), w2t (512..1023), beff (1024) ----
__global__ __launch_bounds__(256) void k_prep(const float* __restrict__ W2,
                                              const float* __restrict__ Wfu,
                                              const float* __restrict__ Wf,
                                              const float* __restrict__ bf,
                                              const float* __restrict__ bfu) {
    int bid = blockIdx.x;
    if (bid < 512) {
        // WeffT[i][f] = sum_l Wfu[f][l] * Wf[l][i] + Wfu[f][256+i]
        __shared__ float wrow[256];
        int f = bid;
        int i = threadIdx.x;
        wrow[i] = Wfu[f * 512 + i];
        __syncthreads();
        float acc = Wfu[f * 512 + 256 + i];
#pragma unroll 4
        for (int l = 0; l < 256; l++)
            acc = fmaf(wrow[l], Wf[l * 256 + i], acc);
        g_WeffT[i * 512 + f] = acc;
    } else if (bid < 1024) {
        int idx = (bid - 512) * 256 + threadIdx.x;  // < 256*512
        int i = idx >> 9;
        int j = idx & 511;
        g_W2T[j * SU_DIM + i] = W2[idx];
    } else {
        // beff[f] = sum_l Wfu[f][l]*bf[l] + bfu[f]   (2 f per thread)
#pragma unroll
        for (int p = 0; p < 2; p++) {
            int f = threadIdx.x + p * 256;
            float acc = bfu[f];
#pragma unroll 4
            for (int l = 0; l < 256; l++)
                acc = fmaf(Wfu[f * 512 + l], bf[l], acc);
            g_beff[f] = acc;
        }
    }
}

// ---------------- K1: cur0 = X @ W1^T + b1, FUSED 16-step spike recurrence ----------------
#define K1_BM 128
#define K1_BN 128
#define K1_BK 16
#define K1_LDS 136

__global__ __launch_bounds__(256, 2) void k_gemm1(const float* __restrict__ X,
                                                  const float* __restrict__ W1,
                                                  const float* __restrict__ b1) {
    __shared__ __align__(16) unsigned char sm[128 * 16 * 16];
    float (*As)[K1_LDS] = (float (*)[K1_LDS])sm;
    float (*Bs)[K1_LDS] = (float (*)[K1_LDS])(sm + K1_BK * K1_LDS * 4);
    unsigned char (*pk)[16][16] = (unsigned char (*)[16][16])sm;  // [row128][t][byte]

    const int n0 = blockIdx.y * K1_BM;
    const int h0 = blockIdx.x * K1_BN;
    const int tid = threadIdx.x;
    const int ty = tid >> 4;
    const int tx = tid & 15;

    const int lrow0 = tid >> 2;
    const int lkq0  = tid & 3;
    const int lrow1 = (tid + 256) >> 2;
    const int lkq1  = (tid + 256) & 3;

    float4 pa0, pa1, pb0, pb1;
    {
        pa0 = *(const float4*)(X  + (size_t)(n0 + lrow0) * 512 + lkq0 * 4);
        pb0 = *(const float4*)(W1 + (size_t)(h0 + lrow0) * 512 + lkq0 * 4);
        pa1 = *(const float4*)(X  + (size_t)(n0 + lrow1) * 512 + lkq1 * 4);
        pb1 = *(const float4*)(W1 + (size_t)(h0 + lrow1) * 512 + lkq1 * 4);
    }

    float acc[8][8];
#pragma unroll
    for (int i = 0; i < 8; i++)
#pragma unroll
        for (int j = 0; j < 8; j++) acc[i][j] = 0.f;

    for (int k0 = 0; k0 < 512; k0 += K1_BK) {
        As[lkq0 * 4 + 0][lrow0] = pa0.x;
        As[lkq0 * 4 + 1][lrow0] = pa0.y;
        As[lkq0 * 4 + 2][lrow0] = pa0.z;
        As[lkq0 * 4 + 3][lrow0] = pa0.w;
        Bs[lkq0 * 4 + 0][lrow0] = pb0.x;
        Bs[lkq0 * 4 + 1][lrow0] = pb0.y;
        Bs[lkq0 * 4 + 2][lrow0] = pb0.z;
        Bs[lkq0 * 4 + 3][lrow0] = pb0.w;
        As[lkq1 * 4 + 0][lrow1] = pa1.x;
        As[lkq1 * 4 + 1][lrow1] = pa1.y;
        As[lkq1 * 4 + 2][lrow1] = pa1.z;
        As[lkq1 * 4 + 3][lrow1] = pa1.w;
        Bs[lkq1 * 4 + 0][lrow1] = pb1.x;
        Bs[lkq1 * 4 + 1][lrow1] = pb1.y;
        Bs[lkq1 * 4 + 2][lrow1] = pb1.z;
        Bs[lkq1 * 4 + 3][lrow1] = pb1.w;
        __syncthreads();

        if (k0 + K1_BK < 512) {
            int kn = k0 + K1_BK;
            pa0 = *(const float4*)(X  + (size_t)(n0 + lrow0) * 512 + kn + lkq0 * 4);
            pb0 = *(const float4*)(W1 + (size_t)(h0 + lrow0) * 512 + kn + lkq0 * 4);
            pa1 = *(const float4*)(X  + (size_t)(n0 + lrow1) * 512 + kn + lkq1 * 4);
            pb1 = *(const float4*)(W1 + (size_t)(h0 + lrow1) * 512 + kn + lkq1 * 4);
        }

#pragma unroll
        for (int k = 0; k < K1_BK; k++) {
            float a[8], b[8];
            *(float4*)(a)     = *(const float4*)&As[k][ty * 8];
            *(float4*)(a + 4) = *(const float4*)&As[k][ty * 8 + 4];
            *(float4*)(b)     = *(const float4*)&Bs[k][tx * 8];
            *(float4*)(b + 4) = *(const float4*)&Bs[k][tx * 8 + 4];
#pragma unroll
            for (int i = 0; i < 8; i++)
#pragma unroll
                for (int j = 0; j < 8; j++)
                    acc[i][j] = fmaf(a[i], b[j], acc[i][j]);
        }
        __syncthreads();
    }

    float bv[8];
#pragma unroll
    for (int j = 0; j < 8; j++) bv[j] = b1[h0 + tx * 8 + j];

#pragma unroll
    for (int i = 0; i < 8; i++) {
        unsigned pw[4] = {0u, 0u, 0u, 0u};
#pragma unroll
        for (int j = 0; j < 8; j++) {
            float c0 = acc[i][j] + bv[j];
            float mem = 0.f, spk = 0.f;
            unsigned bits = 0;
#pragma unroll
            for (int t = 0; t < T_STEPS; t++) {
                float cur = (t == 0) ? c0 : bv[j];
                mem = fmaf(BETA_F, mem, cur) - spk;
                bool s = (mem - THR_F) > 0.f;
                spk = s ? THR_F : 0.f;
                bits |= (unsigned)s << t;
            }
#pragma unroll
            for (int q = 0; q < 4; q++) {
#pragma unroll
                for (int s2 = 0; s2 < 4; s2++)
                    pw[q] |= ((bits >> (q * 4 + s2)) & 1u) << (s2 * 8 + j);
            }
        }
#pragma unroll
        for (int t = 0; t < T_STEPS; t++)
            pk[ty * 8 + i][t][tx] = (unsigned char)((pw[t >> 2] >> ((t & 3) * 8)) & 0xffu);
    }
    __syncthreads();

#pragma unroll
    for (int p = 0; p < 32; p++) {
        int q = tid + p * 256;
        int row = q >> 6;
        int rem = q & 63;
        int t = rem >> 2;
        int w = rem & 3;
        uchar4 b4 = *(const uchar4*)&pk[row][t][w * 4];
        unsigned word = (unsigned)b4.x | ((unsigned)b4.y << 8) |
                        ((unsigned)b4.z << 16) | ((unsigned)b4.w << 24);
        g_spk1[((size_t)(n0 + row) * 16 + t) * 16 + (h0 >> 5) + w] = word;
    }
}

// ---------------- K3: sparse spike-driven layer-2, smem-resident W2 slice ----------------
// 1 block/SM: 153 KB dyn smem = fp32 W2T slice [512][64] (128 KB) + lists[64][192].
// Block = 64 tokens x 64 columns. Slice loaded from L2 ONCE per block (64 MB total
// vs ~1.1 GB when every event pulls rows through L2). Events then hit smem.
#define S2_TOK 64
#define S2_CAP 192
#define S2_W2S_BYTES (512 * 64 * 4)
#define S2_LIST_BYTES (S2_TOK * S2_CAP * 2)
#define S2_SMEM (S2_W2S_BYTES + S2_LIST_BYTES + S2_TOK * 4)

extern __shared__ unsigned char s_dyn[];

__global__ __launch_bounds__(256) void k_spike2(const float* __restrict__ b2) {
    float (*w2s)[64] = (float (*)[64])s_dyn;
    unsigned short (*lists)[S2_CAP] = (unsigned short (*)[S2_CAP])(s_dyn + S2_W2S_BYTES);
    int* counts = (int*)(s_dyn + S2_W2S_BYTES + S2_LIST_BYTES);

    const int tid = threadIdx.x;
    const int lane = tid & 31;
    const int wp = tid >> 5;                 // warp 0..7 -> rows wp*8 .. wp*8+7
    const int n0 = blockIdx.x * S2_TOK;
    const int i0 = blockIdx.y * 64;          // column chunk base

    // cooperative slice load: 512 x 64 floats, float4 per thread x 32
#pragma unroll
    for (int p = 0; p < 32; p++) {
        int e = tid + p * 256;               // 0..8191 float4 units
        int j = e >> 4;
        int c4 = (e & 15) * 4;
        *(float4*)&w2s[j][c4] = *(const float4*)&g_W2T[(size_t)j * SU_DIM + i0 + c4];
    }
    const float2 b2v = *(const float2*)(b2 + i0 + lane * 2);

    // builder role: thread (r_, q_) expands words q_*4 .. q_*4+3 of row r_
    const int r_ = tid >> 2;
    const int q_ = tid & 3;

    float mx[8], my[8], cntx[8], cnty[8];
#pragma unroll
    for (int r = 0; r < 8; r++) { mx[r] = my[r] = cntx[r] = cnty[r] = 0.f; }
    unsigned spx = 0, spy = 0;
    __syncthreads();

    for (int t = 0; t < T_STEPS; t++) {
        __syncthreads();   // previous iteration's readers done with lists

        // ---- phase 1: build event lists (ascending j order) ----
        unsigned wds[4];
        int pc = 0;
#pragma unroll
        for (int ww = 0; ww < 4; ww++) {
            wds[ww] = g_spk1[((size_t)(n0 + r_) * 16 + t) * 16 + q_ * 4 + ww];
            pc += __popc(wds[ww]);
        }
        int inc = pc;
#pragma unroll
        for (int off = 1; off < 4; off <<= 1) {
            int v = __shfl_up_sync(0xffffffffu, inc, off, 4);
            if (q_ >= off) inc += v;
        }
        int base = inc - pc;
        if (q_ == 3) counts[r_] = inc;
#pragma unroll
        for (int ww = 0; ww < 4; ww++) {
            unsigned m = wds[ww];
            int jb = (q_ * 4 + ww) * 32;
            while (m) {
                int b = __ffs(m) - 1;
                m &= m - 1;
                lists[r_][base++] = (unsigned short)(jb + b);
            }
        }
        __syncthreads();

        // ---- phase 2: accumulate from smem, 8 rows/warp, float2/lane, MLP=8 ----
#pragma unroll
        for (int rr = 0; rr < 8; rr++) {
            const int r = wp * 8 + rr;
            float cx = b2v.x, cy = b2v.y;
            const int ne = counts[r];
            int k = 0;
            for (; k + 8 <= ne; k += 8) {
                int j0 = lists[r][k + 0];
                int j1 = lists[r][k + 1];
                int j2 = lists[r][k + 2];
                int j3 = lists[r][k + 3];
                int j4 = lists[r][k + 4];
                int j5 = lists[r][k + 5];
                int j6 = lists[r][k + 6];
                int j7 = lists[r][k + 7];
                float2 v0 = *(const float2*)&w2s[j0][lane * 2];
                float2 v1 = *(const float2*)&w2s[j1][lane * 2];
                float2 v2 = *(const float2*)&w2s[j2][lane * 2];
                float2 v3 = *(const float2*)&w2s[j3][lane * 2];
                float2 v4 = *(const float2*)&w2s[j4][lane * 2];
                float2 v5 = *(const float2*)&w2s[j5][lane * 2];
                float2 v6 = *(const float2*)&w2s[j6][lane * 2];
                float2 v7 = *(const float2*)&w2s[j7][lane * 2];
                cx += ((v0.x + v1.x) + (v2.x + v3.x)) + ((v4.x + v5.x) + (v6.x + v7.x));
                cy += ((v0.y + v1.y) + (v2.y + v3.y)) + ((v4.y + v5.y) + (v6.y + v7.y));
            }
            for (; k < ne; k++) {
                float2 v = *(const float2*)&w2s[lists[r][k]][lane * 2];
                cx += v.x;
                cy += v.y;
            }

            float mmx = fmaf(BETA_F, mx[rr], cx) - (((spx >> rr) & 1u) ? THR_F : 0.f);
            float mmy = fmaf(BETA_F, my[rr], cy) - (((spy >> rr) & 1u) ? THR_F : 0.f);
            mx[rr] = mmx;
            my[rr] = mmy;
            bool sx = (mmx - THR_F) > 0.f;
            bool sy = (mmy - THR_F) > 0.f;
            spx = (spx & ~(1u << rr)) | ((unsigned)sx << rr);
            spy = (spy & ~(1u << rr)) | ((unsigned)sy << rr);
            cntx[rr] += sx ? 1.f : 0.f;
            cnty[rr] += sy ? 1.f : 0.f;
        }
    }

#pragma unroll
    for (int rr = 0; rr < 8; rr++) {
        float2 o;
        o.x = cntx[rr] * (1.f / 16.f);
        o.y = cnty[rr] * (1.f / 16.f);
        *(float2*)(g_sf + (size_t)(n0 + wp * 8 + rr) * SU_DIM + i0 + lane * 2) = o;
    }
}

// ---------------- K4: y = sf @ Weff^T + beff, LayerNorm, ReLU ----------------
__global__ __launch_bounds__(256) void k_final(const float* __restrict__ ln_g,
                                               const float* __restrict__ ln_b,
                                               float* __restrict__ out) {
    __shared__ float Wc[16][512];
    __shared__ float sfc[32][16];

    const int tid = threadIdx.x;
    const int warp = tid >> 5;
    const int lane = tid & 31;
    const int n0 = blockIdx.x * 32;

    float acc[4][16];
#pragma unroll
    for (int r = 0; r < 4; r++)
#pragma unroll
        for (int kk = 0; kk < 16; kk++) acc[r][kk] = 0.f;

    for (int ic = 0; ic < 256; ic += 16) {
        __syncthreads();
#pragma unroll
        for (int p = 0; p < 8; p++) {
            int e4 = tid + p * 256;
            int idx = e4 * 4;
            int ii = idx >> 9;
            int f = idx & 511;
            *(float4*)&Wc[ii][f] = *(const float4*)&g_WeffT[(size_t)(ic + ii) * 512 + f];
        }
#pragma unroll
        for (int p = 0; p < 2; p++) {
            int e = tid + p * 256;
            int row = e >> 4, ii = e & 15;
            sfc[row][ii] = g_sf[(size_t)(n0 + row) * 256 + ic + ii];
        }
        __syncthreads();

#pragma unroll
        for (int ii = 0; ii < 16; ii++) {
            float w[16];
#pragma unroll
            for (int kk = 0; kk < 16; kk++) w[kk] = Wc[ii][lane + 32 * kk];
            float a0 = sfc[warp * 4 + 0][ii];
            float a1 = sfc[warp * 4 + 1][ii];
            float a2 = sfc[warp * 4 + 2][ii];
            float a3 = sfc[warp * 4 + 3][ii];
#pragma unroll
            for (int kk = 0; kk < 16; kk++) {
                acc[0][kk] = fmaf(a0, w[kk], acc[0][kk]);
                acc[1][kk] = fmaf(a1, w[kk], acc[1][kk]);
                acc[2][kk] = fmaf(a2, w[kk], acc[2][kk]);
                acc[3][kk] = fmaf(a3, w[kk], acc[3][kk]);
            }
        }
    }

    float be[16], gg[16], bb[16];
#pragma unroll
    for (int kk = 0; kk < 16; kk++) {
        int f = lane + 32 * kk;
        be[kk] = g_beff[f];
        gg[kk] = ln_g[f];
        bb[kk] = ln_b[f];
    }

#pragma unroll
    for (int r = 0; r < 4; r++) {
        float y[16];
        float s = 0.f;
#pragma unroll
        for (int kk = 0; kk < 16; kk++) {
            y[kk] = acc[r][kk] + be[kk];
            s += y[kk];
        }
#pragma unroll
        for (int o = 16; o > 0; o >>= 1) s += __shfl_xor_sync(0xffffffffu, s, o);
        float mu = s * (1.f / 512.f);
        float sq = 0.f;
#pragma unroll
        for (int kk = 0; kk < 16; kk++) {
            float d = y[kk] - mu;
            sq = fmaf(d, d, sq);
        }
#pragma unroll
        for (int o = 16; o > 0; o >>= 1) sq += __shfl_xor_sync(0xffffffffu, sq, o);
        float rinv = rsqrtf(sq * (1.f / 512.f) + 1e-5f);

        int n = n0 + warp * 4 + r;
#pragma unroll
        for (int kk = 0; kk < 16; kk++) {
            float v = fmaf((y[kk] - mu) * rinv, gg[kk], bb[kk]);
            out[(size_t)n * 512 + lane + 32 * kk] = fmaxf(v, 0.f);
        }
    }
}

// ---------------- launch ----------------
extern "C" void kernel_launch(void* const* d_in, const int* in_sizes, int n_in,
                              void* d_out, int out_size) {
    const float* x    = (const float*)d_in[0];
    const float* W1   = (const float*)d_in[1];
    const float* b1   = (const float*)d_in[2];
    const float* W2   = (const float*)d_in[3];
    const float* b2   = (const float*)d_in[4];
    const float* Wf   = (const float*)d_in[5];
    const float* bf   = (const float*)d_in[6];
    const float* Wfu  = (const float*)d_in[7];
    const float* bfu  = (const float*)d_in[8];
    const float* ln_g = (const float*)d_in[9];
    const float* ln_b = (const float*)d_in[10];
    float* out = (float*)d_out;

    cudaFuncSetAttribute(k_spike2, cudaFuncAttributeMaxDynamicSharedMemorySize, S2_SMEM);

    k_prep<<<1025, 256>>>(W2, Wfu, Wf, bf, bfu);
    k_gemm1<<<dim3(H1_DIM / K1_BN, N_ROWS / K1_BM), 256>>>(x, W1, b1);
    k_spike2<<<dim3(N_ROWS / S2_TOK, 4), 256, S2_SMEM>>>(b2);
    k_final<<<N_ROWS / 32, 256>>>(ln_g, ln_b, out);
}

// round 8
// speedup vs baseline: 1.4127x; 1.4127x over previous
#include <cuda_runtime.h>

#define N_ROWS 8192
#define F_DIM  512
#define H1_DIM 512
#define SU_DIM 256
#define T_STEPS 16
#define BETA_F 0.95f
#define THR_F  1.0f

typedef unsigned long long u64;

// packed fp32x2 helpers (Blackwell native)
__device__ __forceinline__ u64 ffma2(u64 a, u64 b, u64 c) {
    u64 d;
    asm("fma.rn.f32x2 %0, %1, %2, %3;" : "=l"(d) : "l"(a), "l"(b), "l"(c));
    return d;
}
__device__ __forceinline__ u64 pack2(float x) {   // {x, x}
    u64 d;
    asm("mov.b64 %0, {%1, %1};" : "=l"(d) : "f"(x));
    return d;
}
__device__ __forceinline__ float2 unpack2(u64 d) {
    float2 r;
    asm("mov.b64 {%0, %1}, %2;" : "=f"(r.x), "=f"(r.y) : "l"(d));
    return r;
}

// ---------------- scratch (static device globals; no allocations) ----------------
__device__ unsigned g_spk1[N_ROWS * T_STEPS * (H1_DIM / 32)];  // 8 MB  [n][t][w]
__device__ float    g_sf[N_ROWS * SU_DIM];                     // 8 MB
__device__ float    g_W2T[H1_DIM * SU_DIM];                    // [j][i]
__device__ float    g_WeffT[SU_DIM * F_DIM];                   // [i][f]
__device__ float    g_beff[F_DIM];

// ---------------- fused prep: wefft (0..511), w2t (512..1023), beff (1024) ----
__global__ __launch_bounds__(256) void k_prep(const float* __restrict__ W2,
                                              const float* __restrict__ Wfu,
                                              const float* __restrict__ Wf,
                                              const float* __restrict__ bf,
                                              const float* __restrict__ bfu) {
    int bid = blockIdx.x;
    if (bid < 512) {
        __shared__ float wrow[256];
        int f = bid;
        int i = threadIdx.x;
        wrow[i] = Wfu[f * 512 + i];
        __syncthreads();
        float acc = Wfu[f * 512 + 256 + i];
#pragma unroll 4
        for (int l = 0; l < 256; l++)
            acc = fmaf(wrow[l], Wf[l * 256 + i], acc);
        g_WeffT[i * 512 + f] = acc;
    } else if (bid < 1024) {
        int idx = (bid - 512) * 256 + threadIdx.x;
        int i = idx >> 9;
        int j = idx & 511;
        g_W2T[j * SU_DIM + i] = W2[idx];
    } else {
#pragma unroll
        for (int p = 0; p < 2; p++) {
            int f = threadIdx.x + p * 256;
            float acc = bfu[f];
#pragma unroll 4
            for (int l = 0; l < 256; l++)
                acc = fmaf(Wfu[f * 512 + l], bf[l], acc);
            g_beff[f] = acc;
        }
    }
}

// ---------------- K1: cur0 = X @ W1^T + b1, FUSED spike recurrence, f32x2 inner ----
#define K1_BM 128
#define K1_BN 128
#define K1_BK 16
#define K1_LDS 136

__global__ __launch_bounds__(256, 2) void k_gemm1(const float* __restrict__ X,
                                                  const float* __restrict__ W1,
                                                  const float* __restrict__ b1) {
    __shared__ __align__(16) unsigned char sm[128 * 16 * 16];
    float (*As)[K1_LDS] = (float (*)[K1_LDS])sm;
    float (*Bs)[K1_LDS] = (float (*)[K1_LDS])(sm + K1_BK * K1_LDS * 4);
    unsigned char (*pk)[16][16] = (unsigned char (*)[16][16])sm;  // [row128][t][byte]

    const int n0 = blockIdx.y * K1_BM;
    const int h0 = blockIdx.x * K1_BN;
    const int tid = threadIdx.x;
    const int ty = tid >> 4;
    const int tx = tid & 15;

    const int lrow0 = tid >> 2;
    const int lkq0  = tid & 3;
    const int lrow1 = (tid + 256) >> 2;
    const int lkq1  = (tid + 256) & 3;

    float4 pa0, pa1, pb0, pb1;
    {
        pa0 = *(const float4*)(X  + (size_t)(n0 + lrow0) * 512 + lkq0 * 4);
        pb0 = *(const float4*)(W1 + (size_t)(h0 + lrow0) * 512 + lkq0 * 4);
        pa1 = *(const float4*)(X  + (size_t)(n0 + lrow1) * 512 + lkq1 * 4);
        pb1 = *(const float4*)(W1 + (size_t)(h0 + lrow1) * 512 + lkq1 * 4);
    }

    u64 accp[8][4];   // [i][col pair]; pair jp covers cols tx*8 + 2jp, +1
#pragma unroll
    for (int i = 0; i < 8; i++)
#pragma unroll
        for (int jp = 0; jp < 4; jp++) accp[i][jp] = 0ull;

    for (int k0 = 0; k0 < 512; k0 += K1_BK) {
        As[lkq0 * 4 + 0][lrow0] = pa0.x;
        As[lkq0 * 4 + 1][lrow0] = pa0.y;
        As[lkq0 * 4 + 2][lrow0] = pa0.z;
        As[lkq0 * 4 + 3][lrow0] = pa0.w;
        Bs[lkq0 * 4 + 0][lrow0] = pb0.x;
        Bs[lkq0 * 4 + 1][lrow0] = pb0.y;
        Bs[lkq0 * 4 + 2][lrow0] = pb0.z;
        Bs[lkq0 * 4 + 3][lrow0] = pb0.w;
        As[lkq1 * 4 + 0][lrow1] = pa1.x;
        As[lkq1 * 4 + 1][lrow1] = pa1.y;
        As[lkq1 * 4 + 2][lrow1] = pa1.z;
        As[lkq1 * 4 + 3][lrow1] = pa1.w;
        Bs[lkq1 * 4 + 0][lrow1] = pb1.x;
        Bs[lkq1 * 4 + 1][lrow1] = pb1.y;
        Bs[lkq1 * 4 + 2][lrow1] = pb1.z;
        Bs[lkq1 * 4 + 3][lrow1] = pb1.w;
        __syncthreads();

        if (k0 + K1_BK < 512) {
            int kn = k0 + K1_BK;
            pa0 = *(const float4*)(X  + (size_t)(n0 + lrow0) * 512 + kn + lkq0 * 4);
            pb0 = *(const float4*)(W1 + (size_t)(h0 + lrow0) * 512 + kn + lkq0 * 4);
            pa1 = *(const float4*)(X  + (size_t)(n0 + lrow1) * 512 + kn + lkq1 * 4);
            pb1 = *(const float4*)(W1 + (size_t)(h0 + lrow1) * 512 + kn + lkq1 * 4);
        }

#pragma unroll
        for (int k = 0; k < K1_BK; k++) {
            float a[8];
            *(float4*)(a)     = *(const float4*)&As[k][ty * 8];
            *(float4*)(a + 4) = *(const float4*)&As[k][ty * 8 + 4];
            // B pairs loaded directly as packed 64-bit operands
            ulonglong2 t0 = *(const ulonglong2*)&Bs[k][tx * 8];
            ulonglong2 t1 = *(const ulonglong2*)&Bs[k][tx * 8 + 4];
            u64 b2[4] = {t0.x, t0.y, t1.x, t1.y};
#pragma unroll
            for (int i = 0; i < 8; i++) {
                u64 a2 = pack2(a[i]);
#pragma unroll
                for (int jp = 0; jp < 4; jp++)
                    accp[i][jp] = ffma2(a2, b2[jp], accp[i][jp]);
            }
        }
        __syncthreads();
    }

    float bv[8];
#pragma unroll
    for (int j = 0; j < 8; j++) bv[j] = b1[h0 + tx * 8 + j];

    // --- fused spike recurrence + byte packing ---
#pragma unroll
    for (int i = 0; i < 8; i++) {
        unsigned pw[4] = {0u, 0u, 0u, 0u};
#pragma unroll
        for (int jp = 0; jp < 4; jp++) {
            float2 u = unpack2(accp[i][jp]);
#pragma unroll
            for (int h = 0; h < 2; h++) {
                int j = jp * 2 + h;
                float c0 = (h ? u.y : u.x) + bv[j];
                float mem = 0.f, spk = 0.f;
                unsigned bits = 0;
#pragma unroll
                for (int t = 0; t < T_STEPS; t++) {
                    float cur = (t == 0) ? c0 : bv[j];
                    mem = fmaf(BETA_F, mem, cur) - spk;
                    bool s = (mem - THR_F) > 0.f;
                    spk = s ? THR_F : 0.f;
                    bits |= (unsigned)s << t;
                }
#pragma unroll
                for (int q = 0; q < 4; q++) {
#pragma unroll
                    for (int s2 = 0; s2 < 4; s2++)
                        pw[q] |= ((bits >> (q * 4 + s2)) & 1u) << (s2 * 8 + j);
                }
            }
        }
#pragma unroll
        for (int t = 0; t < T_STEPS; t++)
            pk[ty * 8 + i][t][tx] = (unsigned char)((pw[t >> 2] >> ((t & 3) * 8)) & 0xffu);
    }
    __syncthreads();

#pragma unroll
    for (int p = 0; p < 32; p++) {
        int q = tid + p * 256;
        int row = q >> 6;
        int rem = q & 63;
        int t = rem >> 2;
        int w = rem & 3;
        uchar4 b4 = *(const uchar4*)&pk[row][t][w * 4];
        unsigned word = (unsigned)b4.x | ((unsigned)b4.y << 8) |
                        ((unsigned)b4.z << 16) | ((unsigned)b4.w << 24);
        g_spk1[((size_t)(n0 + row) * 16 + t) * 16 + (h0 >> 5) + w] = word;
    }
}

// ---------------- K3: sparse spike-driven layer-2 (round-6 proven version) ----------------
__global__ __launch_bounds__(256) void k_spike2(const float* __restrict__ b2) {
    __shared__ unsigned short lists[16][512];
    __shared__ int counts[16];

    const int tid = threadIdx.x;
    const int n0 = blockIdx.x * 16;
    const int lane = tid & 31;
    const int wp = tid >> 5;
    const int i0 = blockIdx.y * 64 + lane * 2;
    const float2 b2v = *(const float2*)(b2 + i0);
    const float* __restrict__ w2col = g_W2T + i0;

    const int r_ = tid >> 4;
    const int w_ = tid & 15;
    const int sub = tid & 15;

    float mx[2], my[2], cntx[2], cnty[2];
#pragma unroll
    for (int r = 0; r < 2; r++) { mx[r] = my[r] = cntx[r] = cnty[r] = 0.f; }
    unsigned spx = 0, spy = 0;

    for (int t = 0; t < T_STEPS; t++) {
        __syncthreads();

        unsigned word = g_spk1[((size_t)(n0 + r_) * 16 + t) * 16 + w_];
        int pc = __popc(word);
        int inc = pc;
#pragma unroll
        for (int off = 1; off < 16; off <<= 1) {
            int v = __shfl_up_sync(0xffffffffu, inc, off);
            if (sub >= off) inc += v;
        }
        int base = inc - pc;
        if (sub == 15) counts[r_] = inc;
        while (word) {
            int b = __ffs(word) - 1;
            word &= word - 1;
            lists[r_][base++] = (unsigned short)(w_ * 32 + b);
        }
        __syncthreads();

#pragma unroll
        for (int rr = 0; rr < 2; rr++) {
            const int r = wp * 2 + rr;
            float cx = b2v.x, cy = b2v.y;
            const int ne = counts[r];
            int k = 0;
            for (; k + 8 <= ne; k += 8) {
                int j0 = lists[r][k + 0];
                int j1 = lists[r][k + 1];
                int j2 = lists[r][k + 2];
                int j3 = lists[r][k + 3];
                int j4 = lists[r][k + 4];
                int j5 = lists[r][k + 5];
                int j6 = lists[r][k + 6];
                int j7 = lists[r][k + 7];
                float2 v0 = __ldg((const float2*)(w2col + j0 * SU_DIM));
                float2 v1 = __ldg((const float2*)(w2col + j1 * SU_DIM));
                float2 v2 = __ldg((const float2*)(w2col + j2 * SU_DIM));
                float2 v3 = __ldg((const float2*)(w2col + j3 * SU_DIM));
                float2 v4 = __ldg((const float2*)(w2col + j4 * SU_DIM));
                float2 v5 = __ldg((const float2*)(w2col + j5 * SU_DIM));
                float2 v6 = __ldg((const float2*)(w2col + j6 * SU_DIM));
                float2 v7 = __ldg((const float2*)(w2col + j7 * SU_DIM));
                cx += ((v0.x + v1.x) + (v2.x + v3.x)) + ((v4.x + v5.x) + (v6.x + v7.x));
                cy += ((v0.y + v1.y) + (v2.y + v3.y)) + ((v4.y + v5.y) + (v6.y + v7.y));
            }
            for (; k < ne; k++) {
                float2 v = __ldg((const float2*)(w2col + lists[r][k] * SU_DIM));
                cx += v.x;
                cy += v.y;
            }

            float mmx = fmaf(BETA_F, mx[rr], cx) - (((spx >> rr) & 1u) ? THR_F : 0.f);
            float mmy = fmaf(BETA_F, my[rr], cy) - (((spy >> rr) & 1u) ? THR_F : 0.f);
            mx[rr] = mmx;
            my[rr] = mmy;
            bool sx = (mmx - THR_F) > 0.f;
            bool sy = (mmy - THR_F) > 0.f;
            spx = (spx & ~(1u << rr)) | ((unsigned)sx << rr);
            spy = (spy & ~(1u << rr)) | ((unsigned)sy << rr);
            cntx[rr] += sx ? 1.f : 0.f;
            cnty[rr] += sy ? 1.f : 0.f;
        }
    }

#pragma unroll
    for (int rr = 0; rr < 2; rr++) {
        float2 o;
        o.x = cntx[rr] * (1.f / 16.f);
        o.y = cnty[rr] * (1.f / 16.f);
        *(float2*)(g_sf + (size_t)(n0 + wp * 2 + rr) * SU_DIM + i0) = o;
    }
}

// ---------------- K4: y = sf @ Weff^T + beff, LayerNorm, ReLU, f32x2 inner ----------------
// Warp owns 4 rows x 512 cols; thread owns col pairs f = lane*2 + 64*kk (kk 0..7).
__global__ __launch_bounds__(256, 2) void k_final(const float* __restrict__ ln_g,
                                                  const float* __restrict__ ln_b,
                                                  float* __restrict__ out) {
    __shared__ float Wc[16][512];
    __shared__ float sfc[32][16];

    const int tid = threadIdx.x;
    const int warp = tid >> 5;
    const int lane = tid & 31;
    const int n0 = blockIdx.x * 32;

    u64 accp[4][8];   // [row][kk] packed col pair
#pragma unroll
    for (int r = 0; r < 4; r++)
#pragma unroll
        for (int kk = 0; kk < 8; kk++) accp[r][kk] = 0ull;

    for (int ic = 0; ic < 256; ic += 16) {
        __syncthreads();
#pragma unroll
        for (int p = 0; p < 8; p++) {
            int e4 = tid + p * 256;
            int idx = e4 * 4;
            int ii = idx >> 9;
            int f = idx & 511;
            *(float4*)&Wc[ii][f] = *(const float4*)&g_WeffT[(size_t)(ic + ii) * 512 + f];
        }
#pragma unroll
        for (int p = 0; p < 2; p++) {
            int e = tid + p * 256;
            int row = e >> 4, ii = e & 15;
            sfc[row][ii] = g_sf[(size_t)(n0 + row) * 256 + ic + ii];
        }
        __syncthreads();

#pragma unroll
        for (int ii = 0; ii < 16; ii++) {
            u64 w2[8];
#pragma unroll
            for (int kk = 0; kk < 8; kk++)
                w2[kk] = *(const u64*)&Wc[ii][lane * 2 + 64 * kk];
            u64 a0 = pack2(sfc[warp * 4 + 0][ii]);
            u64 a1 = pack2(sfc[warp * 4 + 1][ii]);
            u64 a2 = pack2(sfc[warp * 4 + 2][ii]);
            u64 a3 = pack2(sfc[warp * 4 + 3][ii]);
#pragma unroll
            for (int kk = 0; kk < 8; kk++) {
                accp[0][kk] = ffma2(a0, w2[kk], accp[0][kk]);
                accp[1][kk] = ffma2(a1, w2[kk], accp[1][kk]);
                accp[2][kk] = ffma2(a2, w2[kk], accp[2][kk]);
                accp[3][kk] = ffma2(a3, w2[kk], accp[3][kk]);
            }
        }
    }

    float2 be[8], gg[8], bb[8];
#pragma unroll
    for (int kk = 0; kk < 8; kk++) {
        int f = lane * 2 + 64 * kk;
        be[kk] = *(const float2*)(g_beff + f);
        gg[kk] = *(const float2*)(ln_g + f);
        bb[kk] = *(const float2*)(ln_b + f);
    }

#pragma unroll
    for (int r = 0; r < 4; r++) {
        float2 y[8];
        float s = 0.f;
#pragma unroll
        for (int kk = 0; kk < 8; kk++) {
            float2 u = unpack2(accp[r][kk]);
            y[kk].x = u.x + be[kk].x;
            y[kk].y = u.y + be[kk].y;
            s += y[kk].x + y[kk].y;
        }
#pragma unroll
        for (int o = 16; o > 0; o >>= 1) s += __shfl_xor_sync(0xffffffffu, s, o);
        float mu = s * (1.f / 512.f);
        float sq = 0.f;
#pragma unroll
        for (int kk = 0; kk < 8; kk++) {
            float dx = y[kk].x - mu;
            float dy = y[kk].y - mu;
            sq = fmaf(dx, dx, sq);
            sq = fmaf(dy, dy, sq);
        }
#pragma unroll
        for (int o = 16; o > 0; o >>= 1) sq += __shfl_xor_sync(0xffffffffu, sq, o);
        float rinv = rsqrtf(sq * (1.f / 512.f) + 1e-5f);

        int n = n0 + warp * 4 + r;
#pragma unroll
        for (int kk = 0; kk < 8; kk++) {
            float2 o2;
            o2.x = fmaxf(fmaf((y[kk].x - mu) * rinv, gg[kk].x, bb[kk].x), 0.f);
            o2.y = fmaxf(fmaf((y[kk].y - mu) * rinv, gg[kk].y, bb[kk].y), 0.f);
            *(float2*)(out + (size_t)n * 512 + lane * 2 + 64 * kk) = o2;
        }
    }
}

// ---------------- launch ----------------
extern "C" void kernel_launch(void* const* d_in, const int* in_sizes, int n_in,
                              void* d_out, int out_size) {
    const float* x    = (const float*)d_in[0];
    const float* W1   = (const float*)d_in[1];
    const float* b1   = (const float*)d_in[2];
    const float* W2   = (const float*)d_in[3];
    const float* b2   = (const float*)d_in[4];
    const float* Wf   = (const float*)d_in[5];
    const float* bf   = (const float*)d_in[6];
    const float* Wfu  = (const float*)d_in[7];
    const float* bfu  = (const float*)d_in[8];
    const float* ln_g = (const float*)d_in[9];
    const float* ln_b = (const float*)d_in[10];
    float* out = (float*)d_out;

    k_prep<<<1025, 256>>>(W2, Wfu, Wf, bf, bfu);
    k_gemm1<<<dim3(H1_DIM / K1_BN, N_ROWS / K1_BM), 256>>>(x, W1, b1);
    k_spike2<<<dim3(N_ROWS / 16, 4), 256>>>(b2);
    k_final<<<N_ROWS / 32, 256>>>(ln_g, ln_b, out);
}

// round 9
// speedup vs baseline: 1.4910x; 1.0554x over previous
#include <cuda_runtime.h>
#include <cuda_bf16.h>

#define N_ROWS 8192
#define F_DIM  512
#define H1_DIM 512
#define SU_DIM 256
#define T_STEPS 16
#define BETA_F 0.95f
#define THR_F  1.0f

typedef unsigned int u32;
typedef unsigned long long u64;
typedef unsigned short u16;

// packed fp32x2 helpers (Blackwell native)
__device__ __forceinline__ u64 ffma2(u64 a, u64 b, u64 c) {
    u64 d;
    asm("fma.rn.f32x2 %0, %1, %2, %3;" : "=l"(d) : "l"(a), "l"(b), "l"(c));
    return d;
}
__device__ __forceinline__ u64 pack2(float x) {
    u64 d;
    asm("mov.b64 %0, {%1, %1};" : "=l"(d) : "f"(x));
    return d;
}
__device__ __forceinline__ float2 unpack2(u64 d) {
    float2 r;
    asm("mov.b64 {%0, %1}, %2;" : "=f"(r.x), "=f"(r.y) : "l"(d));
    return r;
}

// bf16 mma: D(16x8) += A(16x16) * B(16x8), fp32 accum
__device__ __forceinline__ void mma_bf16(float (&d)[4], u32 a0, u32 a1, u32 a2, u32 a3,
                                         u32 b0, u32 b1) {
    asm("mma.sync.aligned.m16n8k16.row.col.f32.bf16.bf16.f32 "
        "{%0,%1,%2,%3}, {%4,%5,%6,%7}, {%8,%9}, {%0,%1,%2,%3};"
        : "+f"(d[0]), "+f"(d[1]), "+f"(d[2]), "+f"(d[3])
        : "r"(a0), "r"(a1), "r"(a2), "r"(a3), "r"(b0), "r"(b1));
}

// ---------------- scratch (static device globals; no allocations) ----------------
__device__ unsigned g_spk1[N_ROWS * T_STEPS * (H1_DIM / 32)];  // 8 MB
__device__ __align__(16) u32 g_sfb16[N_ROWS * SU_DIM / 2];     // bf16 cnt pairs, 4 MB
__device__ float g_W2T[H1_DIM * SU_DIM];                       // [j][i]
__device__ __align__(16) u16 g_Whi[F_DIM * SU_DIM];            // bf16 (Weff/16) hi  [f][i]
__device__ __align__(16) u16 g_Wlo[F_DIM * SU_DIM];            // bf16 residual      [f][i]
__device__ float g_beff[F_DIM];

// ---------------- fused prep ----------------
__global__ __launch_bounds__(256) void k_prep(const float* __restrict__ W2,
                                              const float* __restrict__ Wfu,
                                              const float* __restrict__ Wf,
                                              const float* __restrict__ bf,
                                              const float* __restrict__ bfu) {
    int bid = blockIdx.x;
    if (bid < 512) {
        // Weff[f][i] = sum_l Wfu[f][l] * Wf[l][i] + Wfu[f][256+i]; store /16 split-bf16
        __shared__ float wrow[256];
        int f = bid;
        int i = threadIdx.x;
        wrow[i] = Wfu[f * 512 + i];
        __syncthreads();
        float acc = Wfu[f * 512 + 256 + i];
#pragma unroll 4
        for (int l = 0; l < 256; l++)
            acc = fmaf(wrow[l], Wf[l * 256 + i], acc);
        float w = acc * (1.f / 16.f);
        __nv_bfloat16 h = __float2bfloat16(w);
        float hf = __bfloat162float(h);
        __nv_bfloat16 lo = __float2bfloat16(w - hf);
        g_Whi[f * 256 + i] = __bfloat16_as_ushort(h);
        g_Wlo[f * 256 + i] = __bfloat16_as_ushort(lo);
    } else if (bid < 1024) {
        int idx = (bid - 512) * 256 + threadIdx.x;
        int i = idx >> 9;
        int j = idx & 511;
        g_W2T[j * SU_DIM + i] = W2[idx];
    } else {
#pragma unroll
        for (int p = 0; p < 2; p++) {
            int f = threadIdx.x + p * 256;
            float acc = bfu[f];
#pragma unroll 4
            for (int l = 0; l < 256; l++)
                acc = fmaf(Wfu[f * 512 + l], bf[l], acc);
            g_beff[f] = acc;
        }
    }
}

// ---------------- K1: cur0 = X @ W1^T + b1, FUSED spike recurrence, f32x2 inner ----
#define K1_BM 128
#define K1_BN 128
#define K1_BK 16
#define K1_LDS 136

__global__ __launch_bounds__(256, 2) void k_gemm1(const float* __restrict__ X,
                                                  const float* __restrict__ W1,
                                                  const float* __restrict__ b1) {
    __shared__ __align__(16) unsigned char sm[128 * 16 * 16];
    float (*As)[K1_LDS] = (float (*)[K1_LDS])sm;
    float (*Bs)[K1_LDS] = (float (*)[K1_LDS])(sm + K1_BK * K1_LDS * 4);
    unsigned char (*pk)[16][16] = (unsigned char (*)[16][16])sm;

    const int n0 = blockIdx.y * K1_BM;
    const int h0 = blockIdx.x * K1_BN;
    const int tid = threadIdx.x;
    const int ty = tid >> 4;
    const int tx = tid & 15;

    const int lrow0 = tid >> 2;
    const int lkq0  = tid & 3;
    const int lrow1 = (tid + 256) >> 2;
    const int lkq1  = (tid + 256) & 3;

    float4 pa0, pa1, pb0, pb1;
    {
        pa0 = *(const float4*)(X  + (size_t)(n0 + lrow0) * 512 + lkq0 * 4);
        pb0 = *(const float4*)(W1 + (size_t)(h0 + lrow0) * 512 + lkq0 * 4);
        pa1 = *(const float4*)(X  + (size_t)(n0 + lrow1) * 512 + lkq1 * 4);
        pb1 = *(const float4*)(W1 + (size_t)(h0 + lrow1) * 512 + lkq1 * 4);
    }

    u64 accp[8][4];
#pragma unroll
    for (int i = 0; i < 8; i++)
#pragma unroll
        for (int jp = 0; jp < 4; jp++) accp[i][jp] = 0ull;

    for (int k0 = 0; k0 < 512; k0 += K1_BK) {
        As[lkq0 * 4 + 0][lrow0] = pa0.x;
        As[lkq0 * 4 + 1][lrow0] = pa0.y;
        As[lkq0 * 4 + 2][lrow0] = pa0.z;
        As[lkq0 * 4 + 3][lrow0] = pa0.w;
        Bs[lkq0 * 4 + 0][lrow0] = pb0.x;
        Bs[lkq0 * 4 + 1][lrow0] = pb0.y;
        Bs[lkq0 * 4 + 2][lrow0] = pb0.z;
        Bs[lkq0 * 4 + 3][lrow0] = pb0.w;
        As[lkq1 * 4 + 0][lrow1] = pa1.x;
        As[lkq1 * 4 + 1][lrow1] = pa1.y;
        As[lkq1 * 4 + 2][lrow1] = pa1.z;
        As[lkq1 * 4 + 3][lrow1] = pa1.w;
        Bs[lkq1 * 4 + 0][lrow1] = pb1.x;
        Bs[lkq1 * 4 + 1][lrow1] = pb1.y;
        Bs[lkq1 * 4 + 2][lrow1] = pb1.z;
        Bs[lkq1 * 4 + 3][lrow1] = pb1.w;
        __syncthreads();

        if (k0 + K1_BK < 512) {
            int kn = k0 + K1_BK;
            pa0 = *(const float4*)(X  + (size_t)(n0 + lrow0) * 512 + kn + lkq0 * 4);
            pb0 = *(const float4*)(W1 + (size_t)(h0 + lrow0) * 512 + kn + lkq0 * 4);
            pa1 = *(const float4*)(X  + (size_t)(n0 + lrow1) * 512 + kn + lkq1 * 4);
            pb1 = *(const float4*)(W1 + (size_t)(h0 + lrow1) * 512 + kn + lkq1 * 4);
        }

#pragma unroll
        for (int k = 0; k < K1_BK; k++) {
            float a[8];
            *(float4*)(a)     = *(const float4*)&As[k][ty * 8];
            *(float4*)(a + 4) = *(const float4*)&As[k][ty * 8 + 4];
            ulonglong2 t0 = *(const ulonglong2*)&Bs[k][tx * 8];
            ulonglong2 t1 = *(const ulonglong2*)&Bs[k][tx * 8 + 4];
            u64 b2[4] = {t0.x, t0.y, t1.x, t1.y};
#pragma unroll
            for (int i = 0; i < 8; i++) {
                u64 a2 = pack2(a[i]);
#pragma unroll
                for (int jp = 0; jp < 4; jp++)
                    accp[i][jp] = ffma2(a2, b2[jp], accp[i][jp]);
            }
        }
        __syncthreads();
    }

    float bv[8];
#pragma unroll
    for (int j = 0; j < 8; j++) bv[j] = b1[h0 + tx * 8 + j];

#pragma unroll
    for (int i = 0; i < 8; i++) {
        unsigned pw[4] = {0u, 0u, 0u, 0u};
#pragma unroll
        for (int jp = 0; jp < 4; jp++) {
            float2 u = unpack2(accp[i][jp]);
#pragma unroll
            for (int h = 0; h < 2; h++) {
                int j = jp * 2 + h;
                float c0 = (h ? u.y : u.x) + bv[j];
                float mem = 0.f, spk = 0.f;
                unsigned bits = 0;
#pragma unroll
                for (int t = 0; t < T_STEPS; t++) {
                    float cur = (t == 0) ? c0 : bv[j];
                    mem = fmaf(BETA_F, mem, cur) - spk;
                    bool s = (mem - THR_F) > 0.f;
                    spk = s ? THR_F : 0.f;
                    bits |= (unsigned)s << t;
                }
#pragma unroll
                for (int q = 0; q < 4; q++) {
#pragma unroll
                    for (int s2 = 0; s2 < 4; s2++)
                        pw[q] |= ((bits >> (q * 4 + s2)) & 1u) << (s2 * 8 + j);
                }
            }
        }
#pragma unroll
        for (int t = 0; t < T_STEPS; t++)
            pk[ty * 8 + i][t][tx] = (unsigned char)((pw[t >> 2] >> ((t & 3) * 8)) & 0xffu);
    }
    __syncthreads();

#pragma unroll
    for (int p = 0; p < 32; p++) {
        int q = tid + p * 256;
        int row = q >> 6;
        int rem = q & 63;
        int t = rem >> 2;
        int w = rem & 3;
        uchar4 b4 = *(const uchar4*)&pk[row][t][w * 4];
        unsigned word = (unsigned)b4.x | ((unsigned)b4.y << 8) |
                        ((unsigned)b4.z << 16) | ((unsigned)b4.w << 24);
        g_spk1[((size_t)(n0 + row) * 16 + t) * 16 + (h0 >> 5) + w] = word;
    }
}

// ---------------- K3: sparse spike-driven layer-2 (proven version; bf16 cnt out) ----
__global__ __launch_bounds__(256) void k_spike2(const float* __restrict__ b2) {
    __shared__ unsigned short lists[16][512];
    __shared__ int counts[16];

    const int tid = threadIdx.x;
    const int n0 = blockIdx.x * 16;
    const int lane = tid & 31;
    const int wp = tid >> 5;
    const int i0 = blockIdx.y * 64 + lane * 2;
    const float2 b2v = *(const float2*)(b2 + i0);
    const float* __restrict__ w2col = g_W2T + i0;

    const int r_ = tid >> 4;
    const int w_ = tid & 15;
    const int sub = tid & 15;

    float mx[2], my[2], cntx[2], cnty[2];
#pragma unroll
    for (int r = 0; r < 2; r++) { mx[r] = my[r] = cntx[r] = cnty[r] = 0.f; }
    unsigned spx = 0, spy = 0;

    for (int t = 0; t < T_STEPS; t++) {
        __syncthreads();

        unsigned word = g_spk1[((size_t)(n0 + r_) * 16 + t) * 16 + w_];
        int pc = __popc(word);
        int inc = pc;
#pragma unroll
        for (int off = 1; off < 16; off <<= 1) {
            int v = __shfl_up_sync(0xffffffffu, inc, off);
            if (sub >= off) inc += v;
        }
        int base = inc - pc;
        if (sub == 15) counts[r_] = inc;
        while (word) {
            int b = __ffs(word) - 1;
            word &= word - 1;
            lists[r_][base++] = (unsigned short)(w_ * 32 + b);
        }
        __syncthreads();

#pragma unroll
        for (int rr = 0; rr < 2; rr++) {
            const int r = wp * 2 + rr;
            float cx = b2v.x, cy = b2v.y;
            const int ne = counts[r];
            int k = 0;
            for (; k + 8 <= ne; k += 8) {
                int j0 = lists[r][k + 0];
                int j1 = lists[r][k + 1];
                int j2 = lists[r][k + 2];
                int j3 = lists[r][k + 3];
                int j4 = lists[r][k + 4];
                int j5 = lists[r][k + 5];
                int j6 = lists[r][k + 6];
                int j7 = lists[r][k + 7];
                float2 v0 = __ldg((const float2*)(w2col + j0 * SU_DIM));
                float2 v1 = __ldg((const float2*)(w2col + j1 * SU_DIM));
                float2 v2 = __ldg((const float2*)(w2col + j2 * SU_DIM));
                float2 v3 = __ldg((const float2*)(w2col + j3 * SU_DIM));
                float2 v4 = __ldg((const float2*)(w2col + j4 * SU_DIM));
                float2 v5 = __ldg((const float2*)(w2col + j5 * SU_DIM));
                float2 v6 = __ldg((const float2*)(w2col + j6 * SU_DIM));
                float2 v7 = __ldg((const float2*)(w2col + j7 * SU_DIM));
                cx += ((v0.x + v1.x) + (v2.x + v3.x)) + ((v4.x + v5.x) + (v6.x + v7.x));
                cy += ((v0.y + v1.y) + (v2.y + v3.y)) + ((v4.y + v5.y) + (v6.y + v7.y));
            }
            for (; k < ne; k++) {
                float2 v = __ldg((const float2*)(w2col + lists[r][k] * SU_DIM));
                cx += v.x;
                cy += v.y;
            }

            float mmx = fmaf(BETA_F, mx[rr], cx) - (((spx >> rr) & 1u) ? THR_F : 0.f);
            float mmy = fmaf(BETA_F, my[rr], cy) - (((spy >> rr) & 1u) ? THR_F : 0.f);
            mx[rr] = mmx;
            my[rr] = mmy;
            bool sx = (mmx - THR_F) > 0.f;
            bool sy = (mmy - THR_F) > 0.f;
            spx = (spx & ~(1u << rr)) | ((unsigned)sx << rr);
            spy = (spy & ~(1u << rr)) | ((unsigned)sy << rr);
            cntx[rr] += sx ? 1.f : 0.f;
            cnty[rr] += sy ? 1.f : 0.f;
        }
    }

    // write bf16 cnt pairs (integers 0..16: exact truncation to bf16)
#pragma unroll
    for (int rr = 0; rr < 2; rr++) {
        u32 lo = __float_as_uint(cntx[rr]) >> 16;
        u32 hi = __float_as_uint(cnty[rr]) >> 16;
        g_sfb16[((size_t)(n0 + wp * 2 + rr) * SU_DIM + i0) >> 1] = lo | (hi << 16);
    }
}

// ---------------- K4: y = cnt @ (Weff/16)^T + beff, LayerNorm, ReLU  (bf16 mma) ----
// Block 512 thr = 16 warps: 64 tokens x 512 cols. Warp = 16 rows x 128 cols
// = 16 m16n8k16 tiles. A (cnt) exact bf16; B split hi+lo reusing A frags.
#define KF_SMEM (33792 + 18432 + 18432 + 1024)

__global__ __launch_bounds__(512, 1) void k_final(const float* __restrict__ ln_g,
                                                  const float* __restrict__ ln_b,
                                                  float* __restrict__ out) {
    extern __shared__ __align__(16) unsigned char smf[];
    u32*   As32 = (u32*)smf;                         // [64][132] (128 data + pad)
    u32*   Bh32 = (u32*)(smf + 33792);               // [512][9]  (8 data + pad)
    u32*   Bl32 = (u32*)(smf + 33792 + 18432);       // [512][9]
    float* red  = (float*)(smf + 33792 + 36864);     // [64][4]

    const int tid  = threadIdx.x;
    const int warp = tid >> 5, lane = tid & 31;
    const int rg = warp >> 2, cg = warp & 3;
    const int g = lane >> 2, c = lane & 3;
    const int n0 = blockIdx.x * 64;

    // stage A: 64 rows x 128 u32 (bf16 pairs), padded rows for conflict-free frags
#pragma unroll
    for (int p = 0; p < 16; p++) {
        int e = tid + p * 512;
        int row = e >> 7, cw = e & 127;
        As32[row * 132 + cw] = g_sfb16[(size_t)(n0 + row) * 128 + cw];
    }

    float acc[16][4];
#pragma unroll
    for (int nt = 0; nt < 16; nt++)
#pragma unroll
        for (int q = 0; q < 4; q++) acc[nt][q] = 0.f;

    const u32* __restrict__ WhiU = (const u32*)g_Whi;
    const u32* __restrict__ WloU = (const u32*)g_Wlo;

    for (int kc = 0; kc < 16; kc++) {
        __syncthreads();   // prev-chunk readers done (covers A-stage at kc=0)
        {
            const u32* sh = WhiU + tid * 128 + kc * 8;
            const u32* sl = WloU + tid * 128 + kc * 8;
            u32* dh = Bh32 + tid * 9;
            u32* dl = Bl32 + tid * 9;
            uint4 h0 = *(const uint4*)sh;
            uint4 h1 = *(const uint4*)(sh + 4);
            uint4 l0 = *(const uint4*)sl;
            uint4 l1 = *(const uint4*)(sl + 4);
            dh[0] = h0.x; dh[1] = h0.y; dh[2] = h0.z; dh[3] = h0.w;
            dh[4] = h1.x; dh[5] = h1.y; dh[6] = h1.z; dh[7] = h1.w;
            dl[0] = l0.x; dl[1] = l0.y; dl[2] = l0.z; dl[3] = l0.w;
            dl[4] = l1.x; dl[5] = l1.y; dl[6] = l1.z; dl[7] = l1.w;
        }
        __syncthreads();

        int ra = (rg * 16 + g) * 132 + kc * 8;
        int rb = (rg * 16 + g + 8) * 132 + kc * 8;
        u32 a0 = As32[ra + c];
        u32 a1 = As32[rb + c];
        u32 a2 = As32[ra + 4 + c];
        u32 a3 = As32[rb + 4 + c];
#pragma unroll
        for (int nt = 0; nt < 16; nt++) {
            int n = cg * 128 + nt * 8 + g;
            u32 b0 = Bh32[n * 9 + c];
            u32 b1 = Bh32[n * 9 + 4 + c];
            mma_bf16(acc[nt], a0, a1, a2, a3, b0, b1);
            u32 e0 = Bl32[n * 9 + c];
            u32 e1 = Bl32[n * 9 + 4 + c];
            mma_bf16(acc[nt], a0, a1, a2, a3, e0, e1);
        }
    }

    // fold bias into acc
#pragma unroll
    for (int nt = 0; nt < 16; nt++) {
        float2 be = *(const float2*)(g_beff + cg * 128 + nt * 8 + c * 2);
        acc[nt][0] += be.x; acc[nt][1] += be.y;
        acc[nt][2] += be.x; acc[nt][3] += be.y;
    }

    const int rowA = rg * 16 + g, rowB = rowA + 8;

    // mean
    float sA = 0.f, sB = 0.f;
#pragma unroll
    for (int nt = 0; nt < 16; nt++) {
        sA += acc[nt][0] + acc[nt][1];
        sB += acc[nt][2] + acc[nt][3];
    }
    sA += __shfl_xor_sync(0xffffffffu, sA, 1);
    sA += __shfl_xor_sync(0xffffffffu, sA, 2);
    sB += __shfl_xor_sync(0xffffffffu, sB, 1);
    sB += __shfl_xor_sync(0xffffffffu, sB, 2);
    if (c == 0) { red[rowA * 4 + cg] = sA; red[rowB * 4 + cg] = sB; }
    __syncthreads();
    float muA = (red[rowA * 4 + 0] + red[rowA * 4 + 1] +
                 red[rowA * 4 + 2] + red[rowA * 4 + 3]) * (1.f / 512.f);
    float muB = (red[rowB * 4 + 0] + red[rowB * 4 + 1] +
                 red[rowB * 4 + 2] + red[rowB * 4 + 3]) * (1.f / 512.f);
    __syncthreads();

    // variance
    float qA = 0.f, qB = 0.f;
#pragma unroll
    for (int nt = 0; nt < 16; nt++) {
        float d0 = acc[nt][0] - muA, d1 = acc[nt][1] - muA;
        float d2 = acc[nt][2] - muB, d3 = acc[nt][3] - muB;
        qA = fmaf(d0, d0, qA); qA = fmaf(d1, d1, qA);
        qB = fmaf(d2, d2, qB); qB = fmaf(d3, d3, qB);
    }
    qA += __shfl_xor_sync(0xffffffffu, qA, 1);
    qA += __shfl_xor_sync(0xffffffffu, qA, 2);
    qB += __shfl_xor_sync(0xffffffffu, qB, 1);
    qB += __shfl_xor_sync(0xffffffffu, qB, 2);
    if (c == 0) { red[rowA * 4 + cg] = qA; red[rowB * 4 + cg] = qB; }
    __syncthreads();
    float vA = (red[rowA * 4 + 0] + red[rowA * 4 + 1] +
                red[rowA * 4 + 2] + red[rowA * 4 + 3]) * (1.f / 512.f);
    float vB = (red[rowB * 4 + 0] + red[rowB * 4 + 1] +
                red[rowB * 4 + 2] + red[rowB * 4 + 3]) * (1.f / 512.f);
    float rinvA = rsqrtf(vA + 1e-5f);
    float rinvB = rsqrtf(vB + 1e-5f);

    // normalize + affine + relu + store
#pragma unroll
    for (int nt = 0; nt < 16; nt++) {
        int col = cg * 128 + nt * 8 + c * 2;
        float2 gg = *(const float2*)(ln_g + col);
        float2 bb = *(const float2*)(ln_b + col);
        float2 oA, oB;
        oA.x = fmaxf(fmaf((acc[nt][0] - muA) * rinvA, gg.x, bb.x), 0.f);
        oA.y = fmaxf(fmaf((acc[nt][1] - muA) * rinvA, gg.y, bb.y), 0.f);
        oB.x = fmaxf(fmaf((acc[nt][2] - muB) * rinvB, gg.x, bb.x), 0.f);
        oB.y = fmaxf(fmaf((acc[nt][3] - muB) * rinvB, gg.y, bb.y), 0.f);
        *(float2*)(out + (size_t)(n0 + rowA) * 512 + col) = oA;
        *(float2*)(out + (size_t)(n0 + rowB) * 512 + col) = oB;
    }
}

// ---------------- launch ----------------
extern "C" void kernel_launch(void* const* d_in, const int* in_sizes, int n_in,
                              void* d_out, int out_size) {
    const float* x    = (const float*)d_in[0];
    const float* W1   = (const float*)d_in[1];
    const float* b1   = (const float*)d_in[2];
    const float* W2   = (const float*)d_in[3];
    const float* b2   = (const float*)d_in[4];
    const float* Wf   = (const float*)d_in[5];
    const float* bf   = (const float*)d_in[6];
    const float* Wfu  = (const float*)d_in[7];
    const float* bfu  = (const float*)d_in[8];
    const float* ln_g = (const float*)d_in[9];
    const float* ln_b = (const float*)d_in[10];
    float* out = (float*)d_out;

    cudaFuncSetAttribute(k_final, cudaFuncAttributeMaxDynamicSharedMemorySize, KF_SMEM);

    k_prep<<<1025, 256>>>(W2, Wfu, Wf, bf, bfu);
    k_gemm1<<<dim3(H1_DIM / K1_BN, N_ROWS / K1_BM), 256>>>(x, W1, b1);
    k_spike2<<<dim3(N_ROWS / 16, 4), 256>>>(b2);
    k_final<<<N_ROWS / 64, 512, KF_SMEM>>>(ln_g, ln_b, out);
}